// round 15
// baseline (speedup 1.0000x reference)
#include <cuda_runtime.h>
#include <cuda_fp16.h>
#include <cuda_fp8.h>
#include <cstdint>
#include <cstddef>

#define M_DIM 8192
#define N_DIM 4096
#define K_DIM 4096

// ---------------- scratch (static device globals: allowed) ----------------
__device__ __half g_A[(size_t)M_DIM * K_DIM];   // fp16(e4m3(x/s)*s)
__device__ __half g_B[(size_t)N_DIM * K_DIM];   // fp16(e4m3(w)*ws)

// ---------------- helpers ----------------
__device__ __forceinline__ uint32_t smem_u32(const void* p) {
    uint32_t a;
    asm("{ .reg .u64 t; cvta.to.shared.u64 t, %1; cvt.u32.u64 %0, t; }"
        : "=r"(a) : "l"(p));
    return a;
}
__device__ __forceinline__ uint32_t swz128(uint32_t off) {
    return off ^ ((off >> 3) & 0x70u);
}
__device__ __forceinline__ void cp_async16(uint32_t s, const void* g) {
    asm volatile("cp.async.cg.shared.global [%0], [%1], 16;\n" :: "r"(s), "l"(g));
}
#define CP_COMMIT()  asm volatile("cp.async.commit_group;\n" ::: "memory")
#define CP_WAIT(N_)  asm volatile("cp.async.wait_group %0;\n" :: "n"(N_) : "memory")

__device__ __forceinline__ void ldmatrix_x4(uint32_t& r0, uint32_t& r1,
                                            uint32_t& r2, uint32_t& r3,
                                            uint32_t addr) {
    asm volatile("ldmatrix.sync.aligned.m8n8.x4.shared.b16 {%0,%1,%2,%3}, [%4];"
                 : "=r"(r0), "=r"(r1), "=r"(r2), "=r"(r3) : "r"(addr));
}

__device__ __forceinline__ void mma_16816(float* d, const uint32_t* a,
                                          const uint32_t* b) {
    asm volatile(
        "mma.sync.aligned.m16n8k16.row.col.f32.f16.f16.f32 "
        "{%0,%1,%2,%3}, {%4,%5,%6,%7}, {%8,%9}, {%0,%1,%2,%3};"
        : "+f"(d[0]), "+f"(d[1]), "+f"(d[2]), "+f"(d[3])
        : "r"(a[0]), "r"(a[1]), "r"(a[2]), "r"(a[3]), "r"(b[0]), "r"(b[1]));
}

// ---------------- paired e4m3 round-trip (RN-even + satfinite) -------------
__device__ __forceinline__ float2 fp8_roundtrip2(float t0, float t1) {
    float2 f2 = make_float2(t0, t1);
    __nv_fp8x2_storage_t q = __nv_cvt_float2_to_fp8x2(f2, __NV_SATFINITE, __NV_E4M3);
    __half2_raw hr = __nv_cvt_fp8x2_to_halfraw2(q, __NV_E4M3);
    __half2 h2 = *reinterpret_cast<__half2*>(&hr);
    return __half22float2(h2);
}

// ---------------- kernel 1: fused quant (x blocks first, then w blocks) ----
// x: each warp handles TWO 128-blocks (16 lanes per block, 8 values/lane).
// w: each thread handles 8 values (two float4 loads, one uint4 store).
#define QX_BLOCKS 16384     // M rows * 32 kb / (2 kb/warp * 8 warps/block)
#define QW_BLOCKS 8192      // N*K/8 values per thread / 2048 per block

__global__ void __launch_bounds__(256) quant_fused_kernel(
        const float* __restrict__ x, const float* __restrict__ w,
        const float* __restrict__ ws) {
    if (blockIdx.x < QX_BLOCKS) {
        // ---- activation blockwise quant -> fp16 ----
        int gw   = (blockIdx.x * 256 + threadIdx.x) >> 5;   // global warp
        int lane = threadIdx.x & 31;
        int row  = gw >> 4;               // 16 kb-pairs per row
        int kb   = ((gw & 15) << 1) + (lane >> 4);
        int l    = lane & 15;

        const float* src = x + (size_t)row * K_DIM + kb * 128 + l * 8;
        const float4 v0 = *reinterpret_cast<const float4*>(src);
        const float4 v1 = *reinterpret_cast<const float4*>(src + 4);

        float a = fmaxf(fmaxf(fabsf(v0.x), fabsf(v0.y)),
                        fmaxf(fabsf(v0.z), fabsf(v0.w)));
        a = fmaxf(a, fmaxf(fmaxf(fabsf(v1.x), fabsf(v1.y)),
                           fmaxf(fabsf(v1.z), fabsf(v1.w))));
#pragma unroll
        for (int o = 8; o; o >>= 1)       // reduce within 16-lane group
            a = fmaxf(a, __shfl_xor_sync(0xffffffffu, a, o));
        float scale = __fdiv_rn(fmaxf(a, 1e-12f), 448.0f);

        float2 d01 = fp8_roundtrip2(__fdiv_rn(v0.x, scale), __fdiv_rn(v0.y, scale));
        float2 d23 = fp8_roundtrip2(__fdiv_rn(v0.z, scale), __fdiv_rn(v0.w, scale));
        float2 d45 = fp8_roundtrip2(__fdiv_rn(v1.x, scale), __fdiv_rn(v1.y, scale));
        float2 d67 = fp8_roundtrip2(__fdiv_rn(v1.z, scale), __fdiv_rn(v1.w, scale));
        __half2 h01 = __floats2half2_rn(d01.x * scale, d01.y * scale);
        __half2 h23 = __floats2half2_rn(d23.x * scale, d23.y * scale);
        __half2 h45 = __floats2half2_rn(d45.x * scale, d45.y * scale);
        __half2 h67 = __floats2half2_rn(d67.x * scale, d67.y * scale);

        uint4 pack;
        pack.x = *reinterpret_cast<uint32_t*>(&h01);
        pack.y = *reinterpret_cast<uint32_t*>(&h23);
        pack.z = *reinterpret_cast<uint32_t*>(&h45);
        pack.w = *reinterpret_cast<uint32_t*>(&h67);
        *reinterpret_cast<uint4*>(
            g_A + (size_t)row * K_DIM + kb * 128 + l * 8) = pack;
    } else {
        // ---- weight dequant -> fp16 (8 values per thread) ----
        size_t t  = (size_t)(blockIdx.x - QX_BLOCKS) * 256 + threadIdx.x;
        int row   = (int)(t >> 9);           // K/8 = 512 threads per row
        int c8    = (int)(t & 511);          // 8-value chunk within row
        float s   = ws[(row >> 7) * 32 + (c8 >> 4)];   // 16 chunks per 128-blk

        const float* src = w + (size_t)row * K_DIM + c8 * 8;
        float4 v0 = *reinterpret_cast<const float4*>(src);
        float4 v1 = *reinterpret_cast<const float4*>(src + 4);

        float2 d01 = fp8_roundtrip2(v0.x, v0.y);
        float2 d23 = fp8_roundtrip2(v0.z, v0.w);
        float2 d45 = fp8_roundtrip2(v1.x, v1.y);
        float2 d67 = fp8_roundtrip2(v1.z, v1.w);
        __half2 h01 = __floats2half2_rn(d01.x * s, d01.y * s);
        __half2 h23 = __floats2half2_rn(d23.x * s, d23.y * s);
        __half2 h45 = __floats2half2_rn(d45.x * s, d45.y * s);
        __half2 h67 = __floats2half2_rn(d67.x * s, d67.y * s);

        uint4 pack;
        pack.x = *reinterpret_cast<uint32_t*>(&h01);
        pack.y = *reinterpret_cast<uint32_t*>(&h23);
        pack.z = *reinterpret_cast<uint32_t*>(&h45);
        pack.w = *reinterpret_cast<uint32_t*>(&h67);
        *reinterpret_cast<uint4*>(g_B + (size_t)row * K_DIM + c8 * 8) = pack;
    }
}

// ---------------- kernel 2: persistent GEMM out = A @ B^T ------------------
// 128x128 tile, 4 warps (2x2 of 64x64), 2 CTAs/SM, 296 persistent CTAs.
// 3-stage cp.async ring flattened across tiles. Fragment LDSMs issue FIRST
// (critical path); next-slab cp.async split into two half-bursts (A after
// kk0 frags, B after kk1 frags) to smooth LSU pressure.
#define BM 128
#define BN 128
#define BK 64
#define NTHREADS 128
#define STAGES 3
#define SLABS_PER_TILE (K_DIM / BK)        // 64
#define NT_N (N_DIM / BN)                  // 32 n-tiles
#define NTILES ((M_DIM / BM) * NT_N)       // 2048
#define NCTA 296
#define A_STG_BYTES (BM * 128)             // 16384
#define B_STG_BYTES (BN * 128)             // 16384
#define STG_BYTES   (A_STG_BYTES + B_STG_BYTES)   // 32768
#define SMEM_DYN    (STAGES * STG_BYTES)   // 98304

__device__ __forceinline__ void load_half_A(int tid, const __half* Ag,
                                            uint32_t stg) {
#pragma unroll
    for (int i = 0; i < 8; i++) {
        int c = tid + NTHREADS * i;
        int r = c >> 3, seg = c & 7;
        cp_async16(stg + swz128((uint32_t)(r * 128 + seg * 16)),
                   Ag + (size_t)r * K_DIM + seg * 8);
    }
}
__device__ __forceinline__ void load_half_B(int tid, const __half* Bg,
                                            uint32_t stg) {
    uint32_t sB = stg + A_STG_BYTES;
#pragma unroll
    for (int i = 0; i < 8; i++) {
        int c = tid + NTHREADS * i;
        int r = c >> 3, seg = c & 7;
        cp_async16(sB + swz128((uint32_t)(r * 128 + seg * 16)),
                   Bg + (size_t)r * K_DIM + seg * 8);
    }
}

// compute A/B base pointers for flattened slab index ls_l of CTA bid
__device__ __forceinline__ void slab_ptrs(int bid, int ls_l,
                                          const __half** Ag, const __half** Bg) {
    int tl   = bid + (ls_l >> 6) * NCTA;          // tile id
    int slab = ls_l & (SLABS_PER_TILE - 1);
    *Ag = g_A + (size_t)((tl >> 5) * BM) * K_DIM + slab * BK;
    *Bg = g_B + (size_t)((tl & (NT_N - 1)) * BN) * K_DIM + slab * BK;
}

__global__ void __launch_bounds__(NTHREADS, 2)
gemm_kernel(float* __restrict__ out) {
    extern __shared__ char dsm[];
    const uint32_t sb = smem_u32(dsm);

    int tid  = threadIdx.x;
    int wid  = tid >> 5;
    int lane = tid & 31;
    int wm   = wid & 1;        // 2 warps along M (64 rows each)
    int wn   = wid >> 1;       // 2 warps along N (64 cols each)
    int bid  = blockIdx.x;

    // tiles this CTA owns: bid, bid+296, ... (< NTILES)
    const int my_tiles = (NTILES - bid + NCTA - 1) / NCTA;
    const int total_ls = my_tiles * SLABS_PER_TILE;

    // prologue: slabs 0,1 into stages 0,1
    {
        const __half *Ag, *Bg;
        slab_ptrs(bid, 0, &Ag, &Bg);
        load_half_A(tid, Ag, sb);
        load_half_B(tid, Bg, sb);
        CP_COMMIT();
        slab_ptrs(bid, 1, &Ag, &Bg);
        load_half_A(tid, Ag, sb + STG_BYTES);
        load_half_B(tid, Bg, sb + STG_BYTES);
        CP_COMMIT();
    }

    float acc[4][8][4];
#pragma unroll
    for (int mt = 0; mt < 4; mt++)
#pragma unroll
        for (int nt = 0; nt < 8; nt++)
#pragma unroll
            for (int j = 0; j < 4; j++) acc[mt][nt][j] = 0.0f;

    // per-lane ldmatrix addressing pieces
    const uint32_t a_row = (uint32_t)(wm * 64 + (lane & 15));      // + mt*16
    const uint32_t a_ch  = (uint32_t)(lane >> 4);                  // + 2*kk
    const uint32_t b_row = (uint32_t)(wn * 64 + (lane & 7) + ((lane >> 4) << 3));
    const uint32_t b_ch  = (uint32_t)((lane >> 3) & 1);            // + 2*kk

    uint32_t af[4][4];
    uint32_t bf[8][2];

    uint32_t stg_cur = sb;                          // stage of slab ls
    uint32_t stg_nxt = sb + 2u * STG_BYTES;         // stage for slab ls+2

#pragma unroll 1
    for (int ls = 0; ls < total_ls; ls++) {
        CP_WAIT(STAGES - 2);
        __syncthreads();

        const uint32_t sA = stg_cur, sBB = stg_cur + A_STG_BYTES;
        const int lsn = ls + STAGES - 1;
        const bool do_load = (lsn < total_ls);
        const __half *Agn, *Bgn;
        slab_ptrs(bid, lsn, &Agn, &Bgn);

        // kk = 0 fragments (critical path first)
#pragma unroll
        for (int mt = 0; mt < 4; mt++) {
            uint32_t off = (a_row + mt * 16) * 128 + a_ch * 16;
            ldmatrix_x4(af[mt][0], af[mt][1], af[mt][2], af[mt][3],
                        sA + swz128(off));
        }
#pragma unroll
        for (int np = 0; np < 4; np++) {
            uint32_t off = (b_row + np * 16) * 128 + b_ch * 16;
            uint32_t r0, r1, r2, r3;
            ldmatrix_x4(r0, r1, r2, r3, sBB + swz128(off));
            bf[np * 2][0] = r0;     bf[np * 2][1] = r1;
            bf[np * 2 + 1][0] = r2; bf[np * 2 + 1][1] = r3;
        }

        // first half of next-slab loads (A), then kk=0 compute
        if (do_load) load_half_A(tid, Agn, stg_nxt);
#pragma unroll
        for (int mt = 0; mt < 4; mt++)
#pragma unroll
            for (int nt = 0; nt < 8; nt++)
                mma_16816(acc[mt][nt], af[mt], bf[nt]);

        // kk = 1 fragments, second half of loads (B), commit, compute
#pragma unroll
        for (int mt = 0; mt < 4; mt++) {
            uint32_t off = (a_row + mt * 16) * 128 + (a_ch + 2) * 16;
            ldmatrix_x4(af[mt][0], af[mt][1], af[mt][2], af[mt][3],
                        sA + swz128(off));
        }
#pragma unroll
        for (int np = 0; np < 4; np++) {
            uint32_t off = (b_row + np * 16) * 128 + (b_ch + 2) * 16;
            uint32_t r0, r1, r2, r3;
            ldmatrix_x4(r0, r1, r2, r3, sBB + swz128(off));
            bf[np * 2][0] = r0;     bf[np * 2][1] = r1;
            bf[np * 2 + 1][0] = r2; bf[np * 2 + 1][1] = r3;
        }
        if (do_load) load_half_B(tid, Bgn, stg_nxt);
        CP_COMMIT();   // one commit per iteration keeps group accounting aligned
#pragma unroll
        for (int mt = 0; mt < 4; mt++)
#pragma unroll
            for (int nt = 0; nt < 8; nt++)
                mma_16816(acc[mt][nt], af[mt], bf[nt]);

        // rotate stage pointers
        stg_nxt = stg_cur;
        stg_cur += STG_BYTES;
        if (stg_cur == sb + 3u * STG_BYTES) stg_cur = sb;

        // kk = 2..3
#pragma unroll
        for (int kk = 2; kk < 4; kk++) {
#pragma unroll
            for (int mt = 0; mt < 4; mt++) {
                uint32_t off = (a_row + mt * 16) * 128 + (a_ch + 2 * kk) * 16;
                ldmatrix_x4(af[mt][0], af[mt][1], af[mt][2], af[mt][3],
                            sA + swz128(off));
            }
#pragma unroll
            for (int np = 0; np < 4; np++) {
                uint32_t off = (b_row + np * 16) * 128 + (b_ch + 2 * kk) * 16;
                uint32_t r0, r1, r2, r3;
                ldmatrix_x4(r0, r1, r2, r3, sBB + swz128(off));
                bf[np * 2][0] = r0;     bf[np * 2][1] = r1;
                bf[np * 2 + 1][0] = r2; bf[np * 2 + 1][1] = r3;
            }
#pragma unroll
            for (int mt = 0; mt < 4; mt++)
#pragma unroll
                for (int nt = 0; nt < 8; nt++)
                    mma_16816(acc[mt][nt], af[mt], bf[nt]);
        }

        // tile finished? -> epilogue (overlaps next tile's in-flight loads)
        if ((ls & (SLABS_PER_TILE - 1)) == (SLABS_PER_TILE - 1)) {
            int te = bid + (ls >> 6) * NCTA;
            int m_base = (te >> 5) * BM;
            int n_base = (te & (NT_N - 1)) * BN;
            int mrow0 = m_base + wm * 64 + (lane >> 2);
            int ncol0 = n_base + wn * 64 + (lane & 3) * 2;
#pragma unroll
            for (int mt = 0; mt < 4; mt++) {
#pragma unroll
                for (int nt = 0; nt < 8; nt++) {
                    int m0 = mrow0 + mt * 16;
                    int n0 = ncol0 + nt * 8;
                    float2 v0 = {acc[mt][nt][0], acc[mt][nt][1]};
                    float2 v1 = {acc[mt][nt][2], acc[mt][nt][3]};
                    __stcs(reinterpret_cast<float2*>(
                               out + (size_t)m0 * N_DIM + n0), v0);
                    __stcs(reinterpret_cast<float2*>(
                               out + (size_t)(m0 + 8) * N_DIM + n0), v1);
                }
            }
#pragma unroll
            for (int mt = 0; mt < 4; mt++)
#pragma unroll
                for (int nt = 0; nt < 8; nt++)
#pragma unroll
                    for (int j = 0; j < 4; j++) acc[mt][nt][j] = 0.0f;
        }
    }
}

// ---------------- launch ----------------------------------------------------
extern "C" void kernel_launch(void* const* d_in, const int* in_sizes, int n_in,
                              void* d_out, int out_size) {
    const float* x  = (const float*)d_in[0];
    const float* w  = (const float*)d_in[1];
    const float* ws = (const float*)d_in[2];
    float* out = (float*)d_out;

    cudaFuncSetAttribute(gemm_kernel, cudaFuncAttributeMaxDynamicSharedMemorySize,
                         SMEM_DYN);

    quant_fused_kernel<<<QX_BLOCKS + QW_BLOCKS, 256>>>(x, w, ws);
    gemm_kernel<<<NCTA, NTHREADS, SMEM_DYN>>>(out);
}

// round 16
// speedup vs baseline: 1.1281x; 1.1281x over previous
#include <cuda_runtime.h>
#include <cuda_fp16.h>
#include <cuda_fp8.h>
#include <cstdint>
#include <cstddef>

#define M_DIM 8192
#define N_DIM 4096
#define K_DIM 4096

// ---------------- scratch (static device globals: allowed) ----------------
__device__ __half g_A[(size_t)M_DIM * K_DIM];   // fp16(e4m3(x/s)*s)
__device__ __half g_B[(size_t)N_DIM * K_DIM];   // fp16(e4m3(w)*ws)

// ---------------- helpers ----------------
__device__ __forceinline__ uint32_t smem_u32(const void* p) {
    uint32_t a;
    asm("{ .reg .u64 t; cvta.to.shared.u64 t, %1; cvt.u32.u64 %0, t; }"
        : "=r"(a) : "l"(p));
    return a;
}
__device__ __forceinline__ uint32_t swz128(uint32_t off) {
    return off ^ ((off >> 3) & 0x70u);
}
__device__ __forceinline__ void cp_async16(uint32_t s, const void* g) {
    asm volatile("cp.async.cg.shared.global [%0], [%1], 16;\n" :: "r"(s), "l"(g));
}
#define CP_COMMIT()  asm volatile("cp.async.commit_group;\n" ::: "memory")
#define CP_WAIT(N_)  asm volatile("cp.async.wait_group %0;\n" :: "n"(N_) : "memory")

__device__ __forceinline__ void ldmatrix_x4(uint32_t& r0, uint32_t& r1,
                                            uint32_t& r2, uint32_t& r3,
                                            uint32_t addr) {
    asm volatile("ldmatrix.sync.aligned.m8n8.x4.shared.b16 {%0,%1,%2,%3}, [%4];"
                 : "=r"(r0), "=r"(r1), "=r"(r2), "=r"(r3) : "r"(addr));
}

__device__ __forceinline__ void mma_16816(float* d, const uint32_t* a,
                                          const uint32_t* b) {
    asm volatile(
        "mma.sync.aligned.m16n8k16.row.col.f32.f16.f16.f32 "
        "{%0,%1,%2,%3}, {%4,%5,%6,%7}, {%8,%9}, {%0,%1,%2,%3};"
        : "+f"(d[0]), "+f"(d[1]), "+f"(d[2]), "+f"(d[3])
        : "r"(a[0]), "r"(a[1]), "r"(a[2]), "r"(a[3]), "r"(b[0]), "r"(b[1]));
}

// ---------------- paired e4m3 round-trip (RN-even + satfinite) -------------
__device__ __forceinline__ float2 fp8_roundtrip2(float t0, float t1) {
    float2 f2 = make_float2(t0, t1);
    __nv_fp8x2_storage_t q = __nv_cvt_float2_to_fp8x2(f2, __NV_SATFINITE, __NV_E4M3);
    __half2_raw hr = __nv_cvt_fp8x2_to_halfraw2(q, __NV_E4M3);
    __half2 h2 = *reinterpret_cast<__half2*>(&hr);
    return __half22float2(h2);
}

// ---------------- kernel 1: fused quant (x blocks first, then w blocks) ----
// x: each warp handles TWO 128-blocks (16 lanes per block, 8 values/lane).
// w: each thread handles 8 values (two float4 loads, one uint4 store).
#define QX_BLOCKS 16384     // M rows * 32 kb / (2 kb/warp * 8 warps/block)
#define QW_BLOCKS 8192      // N*K/8 values per thread / 2048 per block

__global__ void __launch_bounds__(256) quant_fused_kernel(
        const float* __restrict__ x, const float* __restrict__ w,
        const float* __restrict__ ws) {
    if (blockIdx.x < QX_BLOCKS) {
        // ---- activation blockwise quant -> fp16 ----
        int gw   = (blockIdx.x * 256 + threadIdx.x) >> 5;   // global warp
        int lane = threadIdx.x & 31;
        int row  = gw >> 4;               // 16 kb-pairs per row
        int kb   = ((gw & 15) << 1) + (lane >> 4);
        int l    = lane & 15;

        const float* src = x + (size_t)row * K_DIM + kb * 128 + l * 8;
        const float4 v0 = *reinterpret_cast<const float4*>(src);
        const float4 v1 = *reinterpret_cast<const float4*>(src + 4);

        float a = fmaxf(fmaxf(fabsf(v0.x), fabsf(v0.y)),
                        fmaxf(fabsf(v0.z), fabsf(v0.w)));
        a = fmaxf(a, fmaxf(fmaxf(fabsf(v1.x), fabsf(v1.y)),
                           fmaxf(fabsf(v1.z), fabsf(v1.w))));
#pragma unroll
        for (int o = 8; o; o >>= 1)       // reduce within 16-lane group
            a = fmaxf(a, __shfl_xor_sync(0xffffffffu, a, o));
        float scale = __fdiv_rn(fmaxf(a, 1e-12f), 448.0f);

        float2 d01 = fp8_roundtrip2(__fdiv_rn(v0.x, scale), __fdiv_rn(v0.y, scale));
        float2 d23 = fp8_roundtrip2(__fdiv_rn(v0.z, scale), __fdiv_rn(v0.w, scale));
        float2 d45 = fp8_roundtrip2(__fdiv_rn(v1.x, scale), __fdiv_rn(v1.y, scale));
        float2 d67 = fp8_roundtrip2(__fdiv_rn(v1.z, scale), __fdiv_rn(v1.w, scale));
        __half2 h01 = __floats2half2_rn(d01.x * scale, d01.y * scale);
        __half2 h23 = __floats2half2_rn(d23.x * scale, d23.y * scale);
        __half2 h45 = __floats2half2_rn(d45.x * scale, d45.y * scale);
        __half2 h67 = __floats2half2_rn(d67.x * scale, d67.y * scale);

        uint4 pack;
        pack.x = *reinterpret_cast<uint32_t*>(&h01);
        pack.y = *reinterpret_cast<uint32_t*>(&h23);
        pack.z = *reinterpret_cast<uint32_t*>(&h45);
        pack.w = *reinterpret_cast<uint32_t*>(&h67);
        *reinterpret_cast<uint4*>(
            g_A + (size_t)row * K_DIM + kb * 128 + l * 8) = pack;
    } else {
        // ---- weight dequant -> fp16 (8 values per thread) ----
        size_t t  = (size_t)(blockIdx.x - QX_BLOCKS) * 256 + threadIdx.x;
        int row   = (int)(t >> 9);           // K/8 = 512 threads per row
        int c8    = (int)(t & 511);          // 8-value chunk within row
        float s   = ws[(row >> 7) * 32 + (c8 >> 4)];   // 16 chunks per 128-blk

        const float* src = w + (size_t)row * K_DIM + c8 * 8;
        float4 v0 = *reinterpret_cast<const float4*>(src);
        float4 v1 = *reinterpret_cast<const float4*>(src + 4);

        float2 d01 = fp8_roundtrip2(v0.x, v0.y);
        float2 d23 = fp8_roundtrip2(v0.z, v0.w);
        float2 d45 = fp8_roundtrip2(v1.x, v1.y);
        float2 d67 = fp8_roundtrip2(v1.z, v1.w);
        __half2 h01 = __floats2half2_rn(d01.x * s, d01.y * s);
        __half2 h23 = __floats2half2_rn(d23.x * s, d23.y * s);
        __half2 h45 = __floats2half2_rn(d45.x * s, d45.y * s);
        __half2 h67 = __floats2half2_rn(d67.x * s, d67.y * s);

        uint4 pack;
        pack.x = *reinterpret_cast<uint32_t*>(&h01);
        pack.y = *reinterpret_cast<uint32_t*>(&h23);
        pack.z = *reinterpret_cast<uint32_t*>(&h45);
        pack.w = *reinterpret_cast<uint32_t*>(&h67);
        *reinterpret_cast<uint4*>(g_B + (size_t)row * K_DIM + c8 * 8) = pack;
    }
}

// ---------------- kernel 2: persistent GEMM out = A @ B^T ------------------
// 128x128 tile, 4 warps (2x2 of 64x64), 2 CTAs/SM, 296 persistent CTAs.
// 3-stage cp.async ring flattened across tiles; stage offset carried (no %3).
#define BM 128
#define BN 128
#define BK 64
#define NTHREADS 128
#define STAGES 3
#define SLABS_PER_TILE (K_DIM / BK)        // 64
#define NT_N (N_DIM / BN)                  // 32 n-tiles
#define NTILES ((M_DIM / BM) * NT_N)       // 2048
#define NCTA 296
#define A_STG_BYTES (BM * 128)             // 16384
#define B_STG_BYTES (BN * 128)             // 16384
#define STG_BYTES   (A_STG_BYTES + B_STG_BYTES)   // 32768
#define SMEM_DYN    (STAGES * STG_BYTES)   // 98304

// load one slab given precomputed A/B base pointers into stage 'stg'
__device__ __forceinline__ void load_slab_ptr(int tid, const __half* Ag,
                                              const __half* Bg, uint32_t stg) {
    uint32_t sA = stg, sB = stg + A_STG_BYTES;
#pragma unroll
    for (int i = 0; i < 8; i++) {
        int c = tid + NTHREADS * i;
        int r = c >> 3, seg = c & 7;
        cp_async16(sA + swz128((uint32_t)(r * 128 + seg * 16)),
                   Ag + (size_t)r * K_DIM + seg * 8);
    }
#pragma unroll
    for (int i = 0; i < 8; i++) {
        int c = tid + NTHREADS * i;
        int r = c >> 3, seg = c & 7;
        cp_async16(sB + swz128((uint32_t)(r * 128 + seg * 16)),
                   Bg + (size_t)r * K_DIM + seg * 8);
    }
}

// compute A/B base pointers for flattened slab index ls_l of CTA bid
__device__ __forceinline__ void slab_ptrs(int bid, int ls_l,
                                          const __half** Ag, const __half** Bg) {
    int tl   = bid + (ls_l >> 6) * NCTA;          // tile id
    int slab = ls_l & (SLABS_PER_TILE - 1);
    *Ag = g_A + (size_t)((tl >> 5) * BM) * K_DIM + slab * BK;
    *Bg = g_B + (size_t)((tl & (NT_N - 1)) * BN) * K_DIM + slab * BK;
}

__global__ void __launch_bounds__(NTHREADS, 2)
gemm_kernel(float* __restrict__ out) {
    extern __shared__ char dsm[];
    const uint32_t sb = smem_u32(dsm);

    int tid  = threadIdx.x;
    int wid  = tid >> 5;
    int lane = tid & 31;
    int wm   = wid & 1;        // 2 warps along M (64 rows each)
    int wn   = wid >> 1;       // 2 warps along N (64 cols each)
    int bid  = blockIdx.x;

    // tiles this CTA owns: bid, bid+296, ... (< NTILES)
    const int my_tiles = (NTILES - bid + NCTA - 1) / NCTA;
    const int total_ls = my_tiles * SLABS_PER_TILE;

    // prologue: slabs 0,1 into stages 0,1
    {
        const __half *Ag, *Bg;
        slab_ptrs(bid, 0, &Ag, &Bg);
        load_slab_ptr(tid, Ag, Bg, sb);
        CP_COMMIT();
        slab_ptrs(bid, 1, &Ag, &Bg);
        load_slab_ptr(tid, Ag, Bg, sb + STG_BYTES);
        CP_COMMIT();
    }

    float acc[4][8][4];
#pragma unroll
    for (int mt = 0; mt < 4; mt++)
#pragma unroll
        for (int nt = 0; nt < 8; nt++)
#pragma unroll
            for (int j = 0; j < 4; j++) acc[mt][nt][j] = 0.0f;

    // per-lane ldmatrix addressing pieces
    const uint32_t a_row = (uint32_t)(wm * 64 + (lane & 15));      // + mt*16
    const uint32_t a_ch  = (uint32_t)(lane >> 4);                  // + 2*kk
    const uint32_t b_row = (uint32_t)(wn * 64 + (lane & 7) + ((lane >> 4) << 3));
    const uint32_t b_ch  = (uint32_t)((lane >> 3) & 1);            // + 2*kk

    uint32_t af[4][4];
    uint32_t bf[8][2];

    uint32_t stg_cur = sb;                          // stage of slab ls
    uint32_t stg_nxt = sb + 2u * STG_BYTES;         // stage for slab ls+2

#pragma unroll 1
    for (int ls = 0; ls < total_ls; ls++) {
        CP_WAIT(STAGES - 2);
        __syncthreads();

        const uint32_t sA = stg_cur, sBB = stg_cur + A_STG_BYTES;

        // kk = 0 fragments first (critical path)
#pragma unroll
        for (int mt = 0; mt < 4; mt++) {
            uint32_t off = (a_row + mt * 16) * 128 + a_ch * 16;
            ldmatrix_x4(af[mt][0], af[mt][1], af[mt][2], af[mt][3],
                        sA + swz128(off));
        }
#pragma unroll
        for (int np = 0; np < 4; np++) {
            uint32_t off = (b_row + np * 16) * 128 + b_ch * 16;
            uint32_t r0, r1, r2, r3;
            ldmatrix_x4(r0, r1, r2, r3, sBB + swz128(off));
            bf[np * 2][0] = r0;     bf[np * 2][1] = r1;
            bf[np * 2 + 1][0] = r2; bf[np * 2 + 1][1] = r3;
        }

        // issue cp.async for slab ls+2 (may belong to the next tile)
        {
            int lsn = ls + STAGES - 1;
            if (lsn < total_ls) {
                const __half *Ag, *Bg;
                slab_ptrs(bid, lsn, &Ag, &Bg);
                load_slab_ptr(tid, Ag, Bg, stg_nxt);
            }
            CP_COMMIT();   // (possibly empty) keeps group accounting aligned
        }

        // rotate stage pointers
        stg_nxt = stg_cur;
        stg_cur += STG_BYTES;
        if (stg_cur == sb + 3u * STG_BYTES) stg_cur = sb;

        // kk = 0 compute
#pragma unroll
        for (int mt = 0; mt < 4; mt++)
#pragma unroll
            for (int nt = 0; nt < 8; nt++)
                mma_16816(acc[mt][nt], af[mt], bf[nt]);

        // kk = 1..3
#pragma unroll
        for (int kk = 1; kk < 4; kk++) {
#pragma unroll
            for (int mt = 0; mt < 4; mt++) {
                uint32_t off = (a_row + mt * 16) * 128 + (a_ch + 2 * kk) * 16;
                ldmatrix_x4(af[mt][0], af[mt][1], af[mt][2], af[mt][3],
                            sA + swz128(off));
            }
#pragma unroll
            for (int np = 0; np < 4; np++) {
                uint32_t off = (b_row + np * 16) * 128 + (b_ch + 2 * kk) * 16;
                uint32_t r0, r1, r2, r3;
                ldmatrix_x4(r0, r1, r2, r3, sBB + swz128(off));
                bf[np * 2][0] = r0;     bf[np * 2][1] = r1;
                bf[np * 2 + 1][0] = r2; bf[np * 2 + 1][1] = r3;
            }
#pragma unroll
            for (int mt = 0; mt < 4; mt++)
#pragma unroll
                for (int nt = 0; nt < 8; nt++)
                    mma_16816(acc[mt][nt], af[mt], bf[nt]);
        }

        // tile finished? -> epilogue (overlaps next tile's in-flight loads)
        if ((ls & (SLABS_PER_TILE - 1)) == (SLABS_PER_TILE - 1)) {
            int te = bid + (ls >> 6) * NCTA;
            int m_base = (te >> 5) * BM;
            int n_base = (te & (NT_N - 1)) * BN;
            int mrow0 = m_base + wm * 64 + (lane >> 2);
            int ncol0 = n_base + wn * 64 + (lane & 3) * 2;
#pragma unroll
            for (int mt = 0; mt < 4; mt++) {
#pragma unroll
                for (int nt = 0; nt < 8; nt++) {
                    int m0 = mrow0 + mt * 16;
                    int n0 = ncol0 + nt * 8;
                    float2 v0 = {acc[mt][nt][0], acc[mt][nt][1]};
                    float2 v1 = {acc[mt][nt][2], acc[mt][nt][3]};
                    __stcs(reinterpret_cast<float2*>(
                               out + (size_t)m0 * N_DIM + n0), v0);
                    __stcs(reinterpret_cast<float2*>(
                               out + (size_t)(m0 + 8) * N_DIM + n0), v1);
                }
            }
#pragma unroll
            for (int mt = 0; mt < 4; mt++)
#pragma unroll
                for (int nt = 0; nt < 8; nt++)
#pragma unroll
                    for (int j = 0; j < 4; j++) acc[mt][nt][j] = 0.0f;
        }
    }
}

// ---------------- launch ----------------------------------------------------
extern "C" void kernel_launch(void* const* d_in, const int* in_sizes, int n_in,
                              void* d_out, int out_size) {
    const float* x  = (const float*)d_in[0];
    const float* w  = (const float*)d_in[1];
    const float* ws = (const float*)d_in[2];
    float* out = (float*)d_out;

    cudaFuncSetAttribute(gemm_kernel, cudaFuncAttributeMaxDynamicSharedMemorySize,
                         SMEM_DYN);

    quant_fused_kernel<<<QX_BLOCKS + QW_BLOCKS, 256>>>(x, w, ws);
    gemm_kernel<<<NCTA, NTHREADS, SMEM_DYN>>>(out);
}

// round 17
// speedup vs baseline: 1.1293x; 1.0011x over previous
#include <cuda_runtime.h>
#include <cuda_fp16.h>
#include <cuda_fp8.h>
#include <cstdint>
#include <cstddef>

#define M_DIM 8192
#define N_DIM 4096
#define K_DIM 4096

// ---------------- scratch (static device globals: allowed) ----------------
__device__ __half g_A[(size_t)M_DIM * K_DIM];   // fp16(e4m3(x/s)*s)
__device__ __half g_B[(size_t)N_DIM * K_DIM];   // fp16(e4m3(w)*ws)

// ---------------- helpers ----------------
__device__ __forceinline__ uint32_t smem_u32(const void* p) {
    uint32_t a;
    asm("{ .reg .u64 t; cvta.to.shared.u64 t, %1; cvt.u32.u64 %0, t; }"
        : "=r"(a) : "l"(p));
    return a;
}
__device__ __forceinline__ uint32_t swz128(uint32_t off) {
    return off ^ ((off >> 3) & 0x70u);
}
__device__ __forceinline__ void cp_async16(uint32_t s, const void* g) {
    asm volatile("cp.async.cg.shared.global [%0], [%1], 16;\n" :: "r"(s), "l"(g));
}
#define CP_COMMIT()  asm volatile("cp.async.commit_group;\n" ::: "memory")
#define CP_WAIT(N_)  asm volatile("cp.async.wait_group %0;\n" :: "n"(N_) : "memory")

__device__ __forceinline__ void ldmatrix_x4(uint32_t& r0, uint32_t& r1,
                                            uint32_t& r2, uint32_t& r3,
                                            uint32_t addr) {
    asm volatile("ldmatrix.sync.aligned.m8n8.x4.shared.b16 {%0,%1,%2,%3}, [%4];"
                 : "=r"(r0), "=r"(r1), "=r"(r2), "=r"(r3) : "r"(addr));
}

__device__ __forceinline__ void mma_16816(float* d, const uint32_t* a,
                                          const uint32_t* b) {
    asm volatile(
        "mma.sync.aligned.m16n8k16.row.col.f32.f16.f16.f32 "
        "{%0,%1,%2,%3}, {%4,%5,%6,%7}, {%8,%9}, {%0,%1,%2,%3};"
        : "+f"(d[0]), "+f"(d[1]), "+f"(d[2]), "+f"(d[3])
        : "r"(a[0]), "r"(a[1]), "r"(a[2]), "r"(a[3]), "r"(b[0]), "r"(b[1]));
}

// ---------------- paired e4m3 round-trip (RN-even + satfinite) -------------
__device__ __forceinline__ float2 fp8_roundtrip2(float t0, float t1) {
    float2 f2 = make_float2(t0, t1);
    __nv_fp8x2_storage_t q = __nv_cvt_float2_to_fp8x2(f2, __NV_SATFINITE, __NV_E4M3);
    __half2_raw hr = __nv_cvt_fp8x2_to_halfraw2(q, __NV_E4M3);
    __half2 h2 = *reinterpret_cast<__half2*>(&hr);
    return __half22float2(h2);
}

// ---------------- kernel 1: fused quant (x blocks first, then w blocks) ----
// x: each warp handles TWO 128-blocks (16 lanes per block, 8 values/lane).
// w: each thread handles 8 values (two float4 loads, one uint4 store).
// x/w reads use __ldcs (read-once streaming) so g_A/g_B stay L2-resident.
#define QX_BLOCKS 16384     // M rows * 32 kb / (2 kb/warp * 8 warps/block)
#define QW_BLOCKS 8192      // N*K/8 values per thread / 2048 per block

__global__ void __launch_bounds__(256) quant_fused_kernel(
        const float* __restrict__ x, const float* __restrict__ w,
        const float* __restrict__ ws) {
    if (blockIdx.x < QX_BLOCKS) {
        // ---- activation blockwise quant -> fp16 ----
        int gw   = (blockIdx.x * 256 + threadIdx.x) >> 5;   // global warp
        int lane = threadIdx.x & 31;
        int row  = gw >> 4;               // 16 kb-pairs per row
        int kb   = ((gw & 15) << 1) + (lane >> 4);
        int l    = lane & 15;

        const float* src = x + (size_t)row * K_DIM + kb * 128 + l * 8;
        const float4 v0 = __ldcs(reinterpret_cast<const float4*>(src));
        const float4 v1 = __ldcs(reinterpret_cast<const float4*>(src + 4));

        float a = fmaxf(fmaxf(fabsf(v0.x), fabsf(v0.y)),
                        fmaxf(fabsf(v0.z), fabsf(v0.w)));
        a = fmaxf(a, fmaxf(fmaxf(fabsf(v1.x), fabsf(v1.y)),
                           fmaxf(fabsf(v1.z), fabsf(v1.w))));
#pragma unroll
        for (int o = 8; o; o >>= 1)       // reduce within 16-lane group
            a = fmaxf(a, __shfl_xor_sync(0xffffffffu, a, o));
        float scale = __fdiv_rn(fmaxf(a, 1e-12f), 448.0f);

        float2 d01 = fp8_roundtrip2(__fdiv_rn(v0.x, scale), __fdiv_rn(v0.y, scale));
        float2 d23 = fp8_roundtrip2(__fdiv_rn(v0.z, scale), __fdiv_rn(v0.w, scale));
        float2 d45 = fp8_roundtrip2(__fdiv_rn(v1.x, scale), __fdiv_rn(v1.y, scale));
        float2 d67 = fp8_roundtrip2(__fdiv_rn(v1.z, scale), __fdiv_rn(v1.w, scale));
        __half2 h01 = __floats2half2_rn(d01.x * scale, d01.y * scale);
        __half2 h23 = __floats2half2_rn(d23.x * scale, d23.y * scale);
        __half2 h45 = __floats2half2_rn(d45.x * scale, d45.y * scale);
        __half2 h67 = __floats2half2_rn(d67.x * scale, d67.y * scale);

        uint4 pack;
        pack.x = *reinterpret_cast<uint32_t*>(&h01);
        pack.y = *reinterpret_cast<uint32_t*>(&h23);
        pack.z = *reinterpret_cast<uint32_t*>(&h45);
        pack.w = *reinterpret_cast<uint32_t*>(&h67);
        *reinterpret_cast<uint4*>(
            g_A + (size_t)row * K_DIM + kb * 128 + l * 8) = pack;
    } else {
        // ---- weight dequant -> fp16 (8 values per thread) ----
        size_t t  = (size_t)(blockIdx.x - QX_BLOCKS) * 256 + threadIdx.x;
        int row   = (int)(t >> 9);           // K/8 = 512 threads per row
        int c8    = (int)(t & 511);          // 8-value chunk within row
        float s   = ws[(row >> 7) * 32 + (c8 >> 4)];   // 16 chunks per 128-blk

        const float* src = w + (size_t)row * K_DIM + c8 * 8;
        float4 v0 = __ldcs(reinterpret_cast<const float4*>(src));
        float4 v1 = __ldcs(reinterpret_cast<const float4*>(src + 4));

        float2 d01 = fp8_roundtrip2(v0.x, v0.y);
        float2 d23 = fp8_roundtrip2(v0.z, v0.w);
        float2 d45 = fp8_roundtrip2(v1.x, v1.y);
        float2 d67 = fp8_roundtrip2(v1.z, v1.w);
        __half2 h01 = __floats2half2_rn(d01.x * s, d01.y * s);
        __half2 h23 = __floats2half2_rn(d23.x * s, d23.y * s);
        __half2 h45 = __floats2half2_rn(d45.x * s, d45.y * s);
        __half2 h67 = __floats2half2_rn(d67.x * s, d67.y * s);

        uint4 pack;
        pack.x = *reinterpret_cast<uint32_t*>(&h01);
        pack.y = *reinterpret_cast<uint32_t*>(&h23);
        pack.z = *reinterpret_cast<uint32_t*>(&h45);
        pack.w = *reinterpret_cast<uint32_t*>(&h67);
        *reinterpret_cast<uint4*>(g_B + (size_t)row * K_DIM + c8 * 8) = pack;
    }
}

// ---------------- kernel 2: persistent GEMM out = A @ B^T ------------------
// 128x128 tile, 4 warps (2x2 of 64x64), 2 CTAs/SM, 296 persistent CTAs.
// 3-stage cp.async ring flattened across tiles; stage offset carried (no %3).
#define BM 128
#define BN 128
#define BK 64
#define NTHREADS 128
#define STAGES 3
#define SLABS_PER_TILE (K_DIM / BK)        // 64
#define NT_N (N_DIM / BN)                  // 32 n-tiles
#define NTILES ((M_DIM / BM) * NT_N)       // 2048
#define NCTA 296
#define A_STG_BYTES (BM * 128)             // 16384
#define B_STG_BYTES (BN * 128)             // 16384
#define STG_BYTES   (A_STG_BYTES + B_STG_BYTES)   // 32768
#define SMEM_DYN    (STAGES * STG_BYTES)   // 98304

// load one slab given precomputed A/B base pointers into stage 'stg'
__device__ __forceinline__ void load_slab_ptr(int tid, const __half* Ag,
                                              const __half* Bg, uint32_t stg) {
    uint32_t sA = stg, sB = stg + A_STG_BYTES;
#pragma unroll
    for (int i = 0; i < 8; i++) {
        int c = tid + NTHREADS * i;
        int r = c >> 3, seg = c & 7;
        cp_async16(sA + swz128((uint32_t)(r * 128 + seg * 16)),
                   Ag + (size_t)r * K_DIM + seg * 8);
    }
#pragma unroll
    for (int i = 0; i < 8; i++) {
        int c = tid + NTHREADS * i;
        int r = c >> 3, seg = c & 7;
        cp_async16(sB + swz128((uint32_t)(r * 128 + seg * 16)),
                   Bg + (size_t)r * K_DIM + seg * 8);
    }
}

// compute A/B base pointers for flattened slab index ls_l of CTA bid
__device__ __forceinline__ void slab_ptrs(int bid, int ls_l,
                                          const __half** Ag, const __half** Bg) {
    int tl   = bid + (ls_l >> 6) * NCTA;          // tile id
    int slab = ls_l & (SLABS_PER_TILE - 1);
    *Ag = g_A + (size_t)((tl >> 5) * BM) * K_DIM + slab * BK;
    *Bg = g_B + (size_t)((tl & (NT_N - 1)) * BN) * K_DIM + slab * BK;
}

__global__ void __launch_bounds__(NTHREADS, 2)
gemm_kernel(float* __restrict__ out) {
    extern __shared__ char dsm[];
    const uint32_t sb = smem_u32(dsm);

    int tid  = threadIdx.x;
    int wid  = tid >> 5;
    int lane = tid & 31;
    int wm   = wid & 1;        // 2 warps along M (64 rows each)
    int wn   = wid >> 1;       // 2 warps along N (64 cols each)
    int bid  = blockIdx.x;

    // tiles this CTA owns: bid, bid+296, ... (< NTILES)
    const int my_tiles = (NTILES - bid + NCTA - 1) / NCTA;
    const int total_ls = my_tiles * SLABS_PER_TILE;

    // prologue: slabs 0,1 into stages 0,1
    {
        const __half *Ag, *Bg;
        slab_ptrs(bid, 0, &Ag, &Bg);
        load_slab_ptr(tid, Ag, Bg, sb);
        CP_COMMIT();
        slab_ptrs(bid, 1, &Ag, &Bg);
        load_slab_ptr(tid, Ag, Bg, sb + STG_BYTES);
        CP_COMMIT();
    }

    float acc[4][8][4];
#pragma unroll
    for (int mt = 0; mt < 4; mt++)
#pragma unroll
        for (int nt = 0; nt < 8; nt++)
#pragma unroll
            for (int j = 0; j < 4; j++) acc[mt][nt][j] = 0.0f;

    // per-lane ldmatrix addressing pieces
    const uint32_t a_row = (uint32_t)(wm * 64 + (lane & 15));      // + mt*16
    const uint32_t a_ch  = (uint32_t)(lane >> 4);                  // + 2*kk
    const uint32_t b_row = (uint32_t)(wn * 64 + (lane & 7) + ((lane >> 4) << 3));
    const uint32_t b_ch  = (uint32_t)((lane >> 3) & 1);            // + 2*kk

    uint32_t af[4][4];
    uint32_t bf[8][2];

    uint32_t stg_cur = sb;                          // stage of slab ls
    uint32_t stg_nxt = sb + 2u * STG_BYTES;         // stage for slab ls+2

#pragma unroll 1
    for (int ls = 0; ls < total_ls; ls++) {
        CP_WAIT(STAGES - 2);
        __syncthreads();

        const uint32_t sA = stg_cur, sBB = stg_cur + A_STG_BYTES;

        // kk = 0 fragments first (critical path)
#pragma unroll
        for (int mt = 0; mt < 4; mt++) {
            uint32_t off = (a_row + mt * 16) * 128 + a_ch * 16;
            ldmatrix_x4(af[mt][0], af[mt][1], af[mt][2], af[mt][3],
                        sA + swz128(off));
        }
#pragma unroll
        for (int np = 0; np < 4; np++) {
            uint32_t off = (b_row + np * 16) * 128 + b_ch * 16;
            uint32_t r0, r1, r2, r3;
            ldmatrix_x4(r0, r1, r2, r3, sBB + swz128(off));
            bf[np * 2][0] = r0;     bf[np * 2][1] = r1;
            bf[np * 2 + 1][0] = r2; bf[np * 2 + 1][1] = r3;
        }

        // issue cp.async for slab ls+2 (may belong to the next tile)
        {
            int lsn = ls + STAGES - 1;
            if (lsn < total_ls) {
                const __half *Ag, *Bg;
                slab_ptrs(bid, lsn, &Ag, &Bg);
                load_slab_ptr(tid, Ag, Bg, stg_nxt);
            }
            CP_COMMIT();   // (possibly empty) keeps group accounting aligned
        }

        // rotate stage pointers
        stg_nxt = stg_cur;
        stg_cur += STG_BYTES;
        if (stg_cur == sb + 3u * STG_BYTES) stg_cur = sb;

        // kk = 0 compute
#pragma unroll
        for (int mt = 0; mt < 4; mt++)
#pragma unroll
            for (int nt = 0; nt < 8; nt++)
                mma_16816(acc[mt][nt], af[mt], bf[nt]);

        // kk = 1..3
#pragma unroll
        for (int kk = 1; kk < 4; kk++) {
#pragma unroll
            for (int mt = 0; mt < 4; mt++) {
                uint32_t off = (a_row + mt * 16) * 128 + (a_ch + 2 * kk) * 16;
                ldmatrix_x4(af[mt][0], af[mt][1], af[mt][2], af[mt][3],
                            sA + swz128(off));
            }
#pragma unroll
            for (int np = 0; np < 4; np++) {
                uint32_t off = (b_row + np * 16) * 128 + (b_ch + 2 * kk) * 16;
                uint32_t r0, r1, r2, r3;
                ldmatrix_x4(r0, r1, r2, r3, sBB + swz128(off));
                bf[np * 2][0] = r0;     bf[np * 2][1] = r1;
                bf[np * 2 + 1][0] = r2; bf[np * 2 + 1][1] = r3;
            }
#pragma unroll
            for (int mt = 0; mt < 4; mt++)
#pragma unroll
                for (int nt = 0; nt < 8; nt++)
                    mma_16816(acc[mt][nt], af[mt], bf[nt]);
        }

        // tile finished? -> epilogue (overlaps next tile's in-flight loads)
        if ((ls & (SLABS_PER_TILE - 1)) == (SLABS_PER_TILE - 1)) {
            int te = bid + (ls >> 6) * NCTA;
            int m_base = (te >> 5) * BM;
            int n_base = (te & (NT_N - 1)) * BN;
            int mrow0 = m_base + wm * 64 + (lane >> 2);
            int ncol0 = n_base + wn * 64 + (lane & 3) * 2;
#pragma unroll
            for (int mt = 0; mt < 4; mt++) {
#pragma unroll
                for (int nt = 0; nt < 8; nt++) {
                    int m0 = mrow0 + mt * 16;
                    int n0 = ncol0 + nt * 8;
                    float2 v0 = {acc[mt][nt][0], acc[mt][nt][1]};
                    float2 v1 = {acc[mt][nt][2], acc[mt][nt][3]};
                    __stcs(reinterpret_cast<float2*>(
                               out + (size_t)m0 * N_DIM + n0), v0);
                    __stcs(reinterpret_cast<float2*>(
                               out + (size_t)(m0 + 8) * N_DIM + n0), v1);
                }
            }
#pragma unroll
            for (int mt = 0; mt < 4; mt++)
#pragma unroll
                for (int nt = 0; nt < 8; nt++)
#pragma unroll
                    for (int j = 0; j < 4; j++) acc[mt][nt][j] = 0.0f;
        }
    }
}

// ---------------- launch ----------------------------------------------------
extern "C" void kernel_launch(void* const* d_in, const int* in_sizes, int n_in,
                              void* d_out, int out_size) {
    const float* x  = (const float*)d_in[0];
    const float* w  = (const float*)d_in[1];
    const float* ws = (const float*)d_in[2];
    float* out = (float*)d_out;

    cudaFuncSetAttribute(gemm_kernel, cudaFuncAttributeMaxDynamicSharedMemorySize,
                         SMEM_DYN);

    quant_fused_kernel<<<QX_BLOCKS + QW_BLOCKS, 256>>>(x, w, ws);
    gemm_kernel<<<NCTA, NTHREADS, SMEM_DYN>>>(out);
}